// round 1
// baseline (speedup 1.0000x reference)
#include <cuda_runtime.h>

// ---------------------------------------------------------------------------
// Problem constants (fixed-shape problem)
// ---------------------------------------------------------------------------
#define BB   64
#define TT   2048
#define HID  128
#define G4   512               // 4*HID gates per direction
#define BT   (BB * TT)         // 131072 sequence rows

// Scratch (device globals; no allocation allowed).
// g_xp: gate pre-activations for the CURRENT layer, both directions:
//       [BT][1024]  (cols 0..511 forward gates, 512..1023 backward gates)
// g_out1: layer-0 output sequence [BT][256] (cols 0..127 fwd h, 128..255 bwd h)
__device__ float g_xp[(size_t)BT * 1024];    // 512 MiB
__device__ float g_out1[(size_t)BT * 256];   // 128 MiB

// ---------------------------------------------------------------------------
// Fast, safe activations (fp32; accurate to ~1e-6, no NaN at extremes)
// ---------------------------------------------------------------------------
__device__ __forceinline__ float sigmoid_(float x) {
    return 1.0f / (1.0f + __expf(-x));
}
__device__ __forceinline__ float tanh_(float x) {
    // tanh(x) = 1 - 2/(e^{2x}+1); exp->inf gives 1, exp->0 gives -1 (no NaN)
    return 1.0f - 2.0f / (__expf(2.0f * x) + 1.0f);
}

// ---------------------------------------------------------------------------
// Projection GEMM:  g_xp[m][n] = sum_k A[m][k] * W_dir[n'][k] + bih[n']+bhh[n']
//   A is [BT][K] row-major (K = 32 for layer 0, 256 for layer 1)
//   n < 512 -> forward weights, n >= 512 -> backward weights (n' = n - 512)
// Tiling: 128x128 blocks, BK=16, 256 threads, 8x8 micro-tile, FFMA2 (f32x2).
// ---------------------------------------------------------------------------
#define BM  128
#define BN  128
#define BKK 16

__global__ __launch_bounds__(256)
void proj_gemm_kernel(const float* __restrict__ Aparam, int K, int use_out1,
                      const float* __restrict__ Wf, const float* __restrict__ Wb,
                      const float* __restrict__ bihf, const float* __restrict__ bhhf,
                      const float* __restrict__ bihb, const float* __restrict__ bhhb)
{
    const float* __restrict__ A = use_out1 ? (const float*)g_out1 : Aparam;

    __shared__ __align__(16) float As[BKK * BM];   // As[k][m]
    __shared__ __align__(16) float Ws[BKK * BN];   // Ws[k][n]

    const int n0 = blockIdx.x * BN;
    const int m0 = blockIdx.y * BM;

    const float* Wsel; const float* bihS; const float* bhhS; int nb;
    if (n0 < 512) { Wsel = Wf; bihS = bihf; bhhS = bhhf; nb = n0; }
    else          { Wsel = Wb; bihS = bihb; bhhS = bhhb; nb = n0 - 512; }

    const int tid = threadIdx.x;
    const int tx = tid & 15;   // n-group: cols tx*8 .. tx*8+7
    const int ty = tid >> 4;   // m-group: rows ty*8 .. ty*8+7

    unsigned long long acc[8][4];
#pragma unroll
    for (int i = 0; i < 8; i++)
#pragma unroll
        for (int j = 0; j < 4; j++) acc[i][j] = 0ULL;

    for (int k0 = 0; k0 < K; k0 += BKK) {
        // Load A tile (128 x 16), transpose into As[k][m]
#pragma unroll
        for (int it = 0; it < 2; it++) {
            int idx = tid + it * 256;            // 0..511
            int r = idx >> 2, c4 = idx & 3;
            float4 a4 = *(const float4*)(A + (size_t)(m0 + r) * K + k0 + c4 * 4);
            As[(c4 * 4 + 0) * BM + r] = a4.x;
            As[(c4 * 4 + 1) * BM + r] = a4.y;
            As[(c4 * 4 + 2) * BM + r] = a4.z;
            As[(c4 * 4 + 3) * BM + r] = a4.w;
        }
        // Load W tile (rows nb..nb+127, k k0..k0+15), transpose into Ws[k][n]
#pragma unroll
        for (int it = 0; it < 2; it++) {
            int idx = tid + it * 256;
            int n = idx >> 2, c4 = idx & 3;
            float4 w4 = *(const float4*)(Wsel + (size_t)(nb + n) * K + k0 + c4 * 4);
            Ws[(c4 * 4 + 0) * BN + n] = w4.x;
            Ws[(c4 * 4 + 1) * BN + n] = w4.y;
            Ws[(c4 * 4 + 2) * BN + n] = w4.z;
            Ws[(c4 * 4 + 3) * BN + n] = w4.w;
        }
        __syncthreads();

#pragma unroll
        for (int kk = 0; kk < BKK; kk++) {
            const float* arow = As + kk * BM + ty * 8;
            float4 av0 = *(const float4*)(arow);
            float4 av1 = *(const float4*)(arow + 4);
            float av[8] = {av0.x, av0.y, av0.z, av0.w, av1.x, av1.y, av1.z, av1.w};
            unsigned long long a2[8];
#pragma unroll
            for (int i = 0; i < 8; i++) {
                unsigned int ai = __float_as_uint(av[i]);
                asm("mov.b64 %0, {%1, %1};" : "=l"(a2[i]) : "r"(ai));
            }
            const unsigned long long* wrow =
                (const unsigned long long*)(Ws + kk * BN + tx * 8);
            unsigned long long b0 = wrow[0], b1 = wrow[1], b2 = wrow[2], b3 = wrow[3];
#pragma unroll
            for (int i = 0; i < 8; i++) {
                asm("fma.rn.f32x2 %0, %1, %2, %0;" : "+l"(acc[i][0]) : "l"(a2[i]), "l"(b0));
                asm("fma.rn.f32x2 %0, %1, %2, %0;" : "+l"(acc[i][1]) : "l"(a2[i]), "l"(b1));
                asm("fma.rn.f32x2 %0, %1, %2, %0;" : "+l"(acc[i][2]) : "l"(a2[i]), "l"(b2));
                asm("fma.rn.f32x2 %0, %1, %2, %0;" : "+l"(acc[i][3]) : "l"(a2[i]), "l"(b3));
            }
        }
        __syncthreads();
    }

    // Epilogue: bias add + store
    float bias[8];
#pragma unroll
    for (int j = 0; j < 8; j++) {
        int n = nb + tx * 8 + j;
        bias[j] = bihS[n] + bhhS[n];
    }
#pragma unroll
    for (int i = 0; i < 8; i++) {
        float out[8];
#pragma unroll
        for (int j2 = 0; j2 < 4; j2++) {
            unsigned int lo_u, hi_u;
            asm("mov.b64 {%0, %1}, %2;" : "=r"(lo_u), "=r"(hi_u) : "l"(acc[i][j2]));
            out[2 * j2 + 0] = __uint_as_float(lo_u) + bias[2 * j2 + 0];
            out[2 * j2 + 1] = __uint_as_float(hi_u) + bias[2 * j2 + 1];
        }
        float4* dst = (float4*)(g_xp + (size_t)(m0 + ty * 8 + i) * 1024 + n0 + tx * 8);
        dst[0] = make_float4(out[0], out[1], out[2], out[3]);
        dst[1] = make_float4(out[4], out[5], out[6], out[7]);
    }
}

// ---------------------------------------------------------------------------
// LSTM recurrent scan.
//   grid = (64 batches, 2 directions). 512 threads: thread j owns gate row j.
//   Whh[512][128]: k=0..63 in shared (k-major float4, conflict-free),
//                  k=64..127 register-resident (64 regs/thread).
//   Reads gate pre-activations from g_xp (bias already included).
//   writeSeq!=0  -> write h sequence into g_out1 (layer 0)
//   finalOut!=0  -> write final h into finalOut[b][dir*128 + j] (layer 1)
// ---------------------------------------------------------------------------
#define SCAN_SMEM ((16 * 512) * 16 + (HID + G4) * 4)   // 131072 + 2560 bytes

__global__ __launch_bounds__(512, 1)
void lstm_scan_kernel(const float* __restrict__ WhhF,
                      const float* __restrict__ WhhB,
                      int writeSeq,
                      float* __restrict__ finalOut)
{
    extern __shared__ __align__(16) float smem[];
    float4* Wsh4 = (float4*)smem;                 // [k4 in 0..15][j in 0..511]
    float*  hsh  = smem + 16 * 512 * 4;           // 128 floats
    float*  gsh  = hsh + HID;                     // 512 floats

    const int b   = blockIdx.x;
    const int dir = blockIdx.y;
    const int j   = threadIdx.x;
    const float* __restrict__ Whh = dir ? WhhB : WhhF;

    // Stage weights: row j of Whh as 32 float4 (k pairs of 4)
    const float4* Wrow = (const float4*)(Whh + (size_t)j * HID);
    float4 wreg[16];
#pragma unroll
    for (int k4 = 0; k4 < 16; k4++) {
        Wsh4[k4 * 512 + j] = Wrow[k4];        // k = 0..63 -> shared
        wreg[k4]           = Wrow[16 + k4];   // k = 64..127 -> registers
    }

    float c = 0.0f;
    if (j < HID) hsh[j] = 0.0f;
    __syncthreads();

    const float4* h4 = (const float4*)hsh;

    for (int s = 0; s < TT; s++) {
        const int t = dir ? (TT - 1 - s) : s;
        const size_t row = (size_t)b * TT + t;

        // independent of hsh -> LDG issued early, latency overlapped
        float xv = g_xp[row * 1024 + (size_t)dir * 512 + j];

        float4 accv = make_float4(xv, 0.0f, 0.0f, 0.0f);
#pragma unroll
        for (int k4 = 0; k4 < 16; k4++) {
            float4 w = Wsh4[k4 * 512 + j];
            float4 h = h4[k4];
            accv.x = fmaf(w.x, h.x, accv.x);
            accv.y = fmaf(w.y, h.y, accv.y);
            accv.z = fmaf(w.z, h.z, accv.z);
            accv.w = fmaf(w.w, h.w, accv.w);
        }
#pragma unroll
        for (int k4 = 0; k4 < 16; k4++) {
            float4 h = h4[16 + k4];
            accv.x = fmaf(wreg[k4].x, h.x, accv.x);
            accv.y = fmaf(wreg[k4].y, h.y, accv.y);
            accv.z = fmaf(wreg[k4].z, h.z, accv.z);
            accv.w = fmaf(wreg[k4].w, h.w, accv.w);
        }
        gsh[j] = (accv.x + accv.y) + (accv.z + accv.w);
        __syncthreads();   // gates ready; all hsh reads done

        if (j < HID) {
            float gi = gsh[j];
            float gf = gsh[HID + j];
            float gg = gsh[2 * HID + j];
            float go = gsh[3 * HID + j];
            float iv = sigmoid_(gi);
            float fv = sigmoid_(gf);
            float gv = tanh_(gg);
            float ov = sigmoid_(go);
            c = fv * c + iv * gv;
            float h = ov * tanh_(c);
            hsh[j] = h;
            if (writeSeq)
                g_out1[row * 256 + (size_t)dir * HID + j] = h;
        }
        __syncthreads();   // hsh valid for next step
    }

    if (finalOut != nullptr && j < HID)
        finalOut[(size_t)b * 256 + (size_t)dir * HID + j] = hsh[j];
}

// ---------------------------------------------------------------------------
// kernel_launch: 4 launches, graph-capturable, allocation-free.
// Input order: x, then (Wih,Whh,bih,bhh) for l0f, l0b, l1f, l1b.
// ---------------------------------------------------------------------------
extern "C" void kernel_launch(void* const* d_in, const int* in_sizes, int n_in,
                              void* d_out, int out_size)
{
    const float* x       = (const float*)d_in[0];
    const float* Wih_l0f = (const float*)d_in[1];
    const float* Whh_l0f = (const float*)d_in[2];
    const float* bih_l0f = (const float*)d_in[3];
    const float* bhh_l0f = (const float*)d_in[4];
    const float* Wih_l0b = (const float*)d_in[5];
    const float* Whh_l0b = (const float*)d_in[6];
    const float* bih_l0b = (const float*)d_in[7];
    const float* bhh_l0b = (const float*)d_in[8];
    const float* Wih_l1f = (const float*)d_in[9];
    const float* Whh_l1f = (const float*)d_in[10];
    const float* bih_l1f = (const float*)d_in[11];
    const float* bhh_l1f = (const float*)d_in[12];
    const float* Wih_l1b = (const float*)d_in[13];
    const float* Whh_l1b = (const float*)d_in[14];
    const float* bih_l1b = (const float*)d_in[15];
    const float* bhh_l1b = (const float*)d_in[16];

    float* out = (float*)d_out;

    // >48KB dynamic smem for the scan kernel (idempotent; not a stream op)
    cudaFuncSetAttribute(lstm_scan_kernel,
                         cudaFuncAttributeMaxDynamicSharedMemorySize, SCAN_SMEM);

    dim3 ggrid(1024 / BN * 8 / 8, BT / BM);   // (8, 1024)
    ggrid.x = 1024 / BN;                      // 8 n-blocks

    // Layer 0 input projection: x[BT,32] -> g_xp[BT,1024]
    proj_gemm_kernel<<<ggrid, 256>>>(x, 32, /*use_out1=*/0,
                                     Wih_l0f, Wih_l0b,
                                     bih_l0f, bhh_l0f, bih_l0b, bhh_l0b);

    // Layer 0 scan: g_xp -> g_out1[BT,256]
    lstm_scan_kernel<<<dim3(BB, 2), 512, SCAN_SMEM>>>(
        Whh_l0f, Whh_l0b, /*writeSeq=*/1, /*finalOut=*/nullptr);

    // Layer 1 input projection: g_out1[BT,256] -> g_xp[BT,1024]
    proj_gemm_kernel<<<ggrid, 256>>>(nullptr, 256, /*use_out1=*/1,
                                     Wih_l1f, Wih_l1b,
                                     bih_l1f, bhh_l1f, bih_l1b, bhh_l1b);

    // Layer 1 scan: g_xp -> final hidden states in d_out[64,256]
    lstm_scan_kernel<<<dim3(BB, 2), 512, SCAN_SMEM>>>(
        Whh_l1f, Whh_l1b, /*writeSeq=*/0, /*finalOut=*/out);
}

// round 2
// speedup vs baseline: 1.5784x; 1.5784x over previous
#include <cuda_runtime.h>

// ---------------------------------------------------------------------------
// Problem constants (fixed-shape problem)
// ---------------------------------------------------------------------------
#define BB   64
#define TT   2048
#define HID  128
#define BT   (BB * TT)         // 131072 sequence rows

// Scratch (device globals; no allocation allowed).
__device__ float g_xp[(size_t)BT * 1024];    // gate preacts, fwd|bwd (512 MiB)
__device__ float g_out1[(size_t)BT * 256];   // layer-0 output seq (128 MiB)

// ---------------------------------------------------------------------------
// Activations (fp32; no NaN at extremes)
// ---------------------------------------------------------------------------
__device__ __forceinline__ float sigmoid_(float x) {
    return 1.0f / (1.0f + __expf(-x));
}
__device__ __forceinline__ float tanh_(float x) {
    return 1.0f - 2.0f / (__expf(2.0f * x) + 1.0f);
}

// ---------------------------------------------------------------------------
// Projection GEMM (unchanged from R1): g_xp = A @ W^T + bias
// ---------------------------------------------------------------------------
#define BM  128
#define BN  128
#define BKK 16

__global__ __launch_bounds__(256)
void proj_gemm_kernel(const float* __restrict__ Aparam, int K, int use_out1,
                      const float* __restrict__ Wf, const float* __restrict__ Wb,
                      const float* __restrict__ bihf, const float* __restrict__ bhhf,
                      const float* __restrict__ bihb, const float* __restrict__ bhhb)
{
    const float* __restrict__ A = use_out1 ? (const float*)g_out1 : Aparam;

    __shared__ __align__(16) float As[BKK * BM];   // As[k][m]
    __shared__ __align__(16) float Ws[BKK * BN];   // Ws[k][n]

    const int n0 = blockIdx.x * BN;
    const int m0 = blockIdx.y * BM;

    const float* Wsel; const float* bihS; const float* bhhS; int nb;
    if (n0 < 512) { Wsel = Wf; bihS = bihf; bhhS = bhhf; nb = n0; }
    else          { Wsel = Wb; bihS = bihb; bhhS = bhhb; nb = n0 - 512; }

    const int tid = threadIdx.x;
    const int tx = tid & 15;
    const int ty = tid >> 4;

    unsigned long long acc[8][4];
#pragma unroll
    for (int i = 0; i < 8; i++)
#pragma unroll
        for (int j = 0; j < 4; j++) acc[i][j] = 0ULL;

    for (int k0 = 0; k0 < K; k0 += BKK) {
#pragma unroll
        for (int it = 0; it < 2; it++) {
            int idx = tid + it * 256;
            int r = idx >> 2, c4 = idx & 3;
            float4 a4 = *(const float4*)(A + (size_t)(m0 + r) * K + k0 + c4 * 4);
            As[(c4 * 4 + 0) * BM + r] = a4.x;
            As[(c4 * 4 + 1) * BM + r] = a4.y;
            As[(c4 * 4 + 2) * BM + r] = a4.z;
            As[(c4 * 4 + 3) * BM + r] = a4.w;
        }
#pragma unroll
        for (int it = 0; it < 2; it++) {
            int idx = tid + it * 256;
            int n = idx >> 2, c4 = idx & 3;
            float4 w4 = *(const float4*)(Wsel + (size_t)(nb + n) * K + k0 + c4 * 4);
            Ws[(c4 * 4 + 0) * BN + n] = w4.x;
            Ws[(c4 * 4 + 1) * BN + n] = w4.y;
            Ws[(c4 * 4 + 2) * BN + n] = w4.z;
            Ws[(c4 * 4 + 3) * BN + n] = w4.w;
        }
        __syncthreads();

#pragma unroll
        for (int kk = 0; kk < BKK; kk++) {
            const float* arow = As + kk * BM + ty * 8;
            float4 av0 = *(const float4*)(arow);
            float4 av1 = *(const float4*)(arow + 4);
            float av[8] = {av0.x, av0.y, av0.z, av0.w, av1.x, av1.y, av1.z, av1.w};
            unsigned long long a2[8];
#pragma unroll
            for (int i = 0; i < 8; i++) {
                unsigned int ai = __float_as_uint(av[i]);
                asm("mov.b64 %0, {%1, %1};" : "=l"(a2[i]) : "r"(ai));
            }
            const unsigned long long* wrow =
                (const unsigned long long*)(Ws + kk * BN + tx * 8);
            unsigned long long b0 = wrow[0], b1 = wrow[1], b2 = wrow[2], b3 = wrow[3];
#pragma unroll
            for (int i = 0; i < 8; i++) {
                asm("fma.rn.f32x2 %0, %1, %2, %0;" : "+l"(acc[i][0]) : "l"(a2[i]), "l"(b0));
                asm("fma.rn.f32x2 %0, %1, %2, %0;" : "+l"(acc[i][1]) : "l"(a2[i]), "l"(b1));
                asm("fma.rn.f32x2 %0, %1, %2, %0;" : "+l"(acc[i][2]) : "l"(a2[i]), "l"(b2));
                asm("fma.rn.f32x2 %0, %1, %2, %0;" : "+l"(acc[i][3]) : "l"(a2[i]), "l"(b3));
            }
        }
        __syncthreads();
    }

    float bias[8];
#pragma unroll
    for (int j = 0; j < 8; j++) {
        int n = nb + tx * 8 + j;
        bias[j] = bihS[n] + bhhS[n];
    }
#pragma unroll
    for (int i = 0; i < 8; i++) {
        float out[8];
#pragma unroll
        for (int j2 = 0; j2 < 4; j2++) {
            unsigned int lo_u, hi_u;
            asm("mov.b64 {%0, %1}, %2;" : "=r"(lo_u), "=r"(hi_u) : "l"(acc[i][j2]));
            out[2 * j2 + 0] = __uint_as_float(lo_u) + bias[2 * j2 + 0];
            out[2 * j2 + 1] = __uint_as_float(hi_u) + bias[2 * j2 + 1];
        }
        float4* dst = (float4*)(g_xp + (size_t)(m0 + ty * 8 + i) * 1024 + n0 + tx * 8);
        dst[0] = make_float4(out[0], out[1], out[2], out[3]);
        dst[1] = make_float4(out[4], out[5], out[6], out[7]);
    }
}

// ---------------------------------------------------------------------------
// LSTM recurrent scan, v2.
//   grid = (64 batches, 2 directions), 256 threads.
//   Thread t: u = t>>1 (hidden unit 0..127), kh = t&1 (k-half).
//   Owns all 4 gates of unit u over k in [kh*64, kh*64+64).
//   Weights: 24 f32x2 pairs/gate in REGISTERS (192 regs), 8 pairs/gate in smem.
//   Inner product via fma.rn.f32x2; i/f/g/o reduction via shfl.xor(1);
//   h double-buffered in smem -> ONE __syncthreads per step.
// ---------------------------------------------------------------------------
#define NPREG 24                         // register-resident pairs per gate
#define NPSM  (32 - NPREG)               // smem-resident pairs per gate (8)
#define WSM_ULL (4 * NPSM * 256)         // 8192 ull = 64 KiB
#define SCAN_SMEM (WSM_ULL * 8 + 2 * HID * 4)

__global__ __launch_bounds__(256, 1)
void lstm_scan_kernel(const float* __restrict__ WhhF,
                      const float* __restrict__ WhhB,
                      int writeSeq,
                      float* __restrict__ finalOut)
{
    extern __shared__ __align__(16) float smem[];
    unsigned long long* Wsm = (unsigned long long*)smem;       // [4*NPSM][256]
    float* hbuf = smem + WSM_ULL * 2;                          // [2][128]

    const int b   = blockIdx.x;
    const int dir = blockIdx.y;
    const int t   = threadIdx.x;
    const int u   = t >> 1;
    const int kh  = t & 1;
    const int K0  = kh * 64;
    const float* __restrict__ Whh = dir ? WhhB : WhhF;

    // ---- stage weights: regs (pairs 0..NPREG-1) + smem (pairs NPREG..31) ----
    unsigned long long wr[4][NPREG];
#pragma unroll
    for (int g = 0; g < 4; g++) {
        const unsigned long long* row =
            (const unsigned long long*)(Whh + (size_t)(g * 128 + u) * HID + K0);
#pragma unroll
        for (int p = 0; p < NPREG; p++) wr[g][p] = row[p];
#pragma unroll
        for (int q = 0; q < NPSM; q++)
            Wsm[(g * NPSM + q) * 256 + t] = row[NPREG + q];
    }

    if (t < 2 * HID) hbuf[t] = 0.0f;

    const size_t xbase = (size_t)b * TT * 1024 + (size_t)dir * 512 + u;
    const size_t obase = (size_t)b * TT * 256 + (size_t)dir * HID + u;

    // prefetch xv for step 0
    float xv0 = 0.f, xv1 = 0.f, xv2 = 0.f, xv3 = 0.f;
    {
        int t0 = dir ? (TT - 1) : 0;
        const float* xp = g_xp + xbase + (size_t)t0 * 1024;
        if (kh == 0) { xv0 = xp[0]; xv1 = xp[128]; xv2 = xp[256]; xv3 = xp[384]; }
    }

    __syncthreads();

    float cval = 0.0f, hval = 0.0f;
    int par = 0;

    for (int s = 0; s < TT; s++) {
        const int tcur = dir ? (TT - 1 - s) : s;

        // prefetch next step's gate preacts (covered by the FMA phase)
        float nx0 = 0.f, nx1 = 0.f, nx2 = 0.f, nx3 = 0.f;
        {
            int sn = (s + 1 < TT) ? (s + 1) : s;
            int tn = dir ? (TT - 1 - sn) : sn;
            const float* xpn = g_xp + xbase + (size_t)tn * 1024;
            if (kh == 0) { nx0 = xpn[0]; nx1 = xpn[128]; nx2 = xpn[256]; nx3 = xpn[384]; }
        }

        // ---- FMA phase: 4 gates x 32 f32x2 pairs over this thread's k-half --
        const float* hc = hbuf + par * HID + K0;
        unsigned long long a0 = 0ULL, a1 = 0ULL, a2 = 0ULL, a3 = 0ULL;
#pragma unroll
        for (int i = 0; i < 16; i++) {          // pairs (2i, 2i+1)
            ulonglong2 hv = *(const ulonglong2*)(hc + 4 * i);
            unsigned long long w0a, w0b, w0c, w0d, w1a, w1b, w1c, w1d;
            if (2 * i + 1 < NPREG) {
                w0a = wr[0][2 * i];     w1a = wr[0][2 * i + 1];
                w0b = wr[1][2 * i];     w1b = wr[1][2 * i + 1];
                w0c = wr[2][2 * i];     w1c = wr[2][2 * i + 1];
                w0d = wr[3][2 * i];     w1d = wr[3][2 * i + 1];
            } else {
                int q0 = 2 * i - NPREG;
                w0a = Wsm[(0 * NPSM + q0) * 256 + t];
                w1a = Wsm[(0 * NPSM + q0 + 1) * 256 + t];
                w0b = Wsm[(1 * NPSM + q0) * 256 + t];
                w1b = Wsm[(1 * NPSM + q0 + 1) * 256 + t];
                w0c = Wsm[(2 * NPSM + q0) * 256 + t];
                w1c = Wsm[(2 * NPSM + q0 + 1) * 256 + t];
                w0d = Wsm[(3 * NPSM + q0) * 256 + t];
                w1d = Wsm[(3 * NPSM + q0 + 1) * 256 + t];
            }
            asm("fma.rn.f32x2 %0, %1, %2, %0;" : "+l"(a0) : "l"(w0a), "l"(hv.x));
            asm("fma.rn.f32x2 %0, %1, %2, %0;" : "+l"(a1) : "l"(w0b), "l"(hv.x));
            asm("fma.rn.f32x2 %0, %1, %2, %0;" : "+l"(a2) : "l"(w0c), "l"(hv.x));
            asm("fma.rn.f32x2 %0, %1, %2, %0;" : "+l"(a3) : "l"(w0d), "l"(hv.x));
            asm("fma.rn.f32x2 %0, %1, %2, %0;" : "+l"(a0) : "l"(w1a), "l"(hv.y));
            asm("fma.rn.f32x2 %0, %1, %2, %0;" : "+l"(a1) : "l"(w1b), "l"(hv.y));
            asm("fma.rn.f32x2 %0, %1, %2, %0;" : "+l"(a2) : "l"(w1c), "l"(hv.y));
            asm("fma.rn.f32x2 %0, %1, %2, %0;" : "+l"(a3) : "l"(w1d), "l"(hv.y));
        }

        // ---- reduce: horizontal add + partner (other k-half) via shfl ------
        float s0, s1, s2, s3;
        {
            unsigned int lo, hi;
            asm("mov.b64 {%0, %1}, %2;" : "=r"(lo), "=r"(hi) : "l"(a0));
            s0 = __uint_as_float(lo) + __uint_as_float(hi);
            asm("mov.b64 {%0, %1}, %2;" : "=r"(lo), "=r"(hi) : "l"(a1));
            s1 = __uint_as_float(lo) + __uint_as_float(hi);
            asm("mov.b64 {%0, %1}, %2;" : "=r"(lo), "=r"(hi) : "l"(a2));
            s2 = __uint_as_float(lo) + __uint_as_float(hi);
            asm("mov.b64 {%0, %1}, %2;" : "=r"(lo), "=r"(hi) : "l"(a3));
            s3 = __uint_as_float(lo) + __uint_as_float(hi);
        }
        s0 += __shfl_xor_sync(0xffffffffu, s0, 1);
        s1 += __shfl_xor_sync(0xffffffffu, s1, 1);
        s2 += __shfl_xor_sync(0xffffffffu, s2, 1);
        s3 += __shfl_xor_sync(0xffffffffu, s3, 1);

        if (kh == 0) {
            float gi = s0 + xv0;
            float gf = s1 + xv1;
            float gg = s2 + xv2;
            float go = s3 + xv3;
            float iv = sigmoid_(gi);
            float fv = sigmoid_(gf);
            float gv = tanh_(gg);
            float ov = sigmoid_(go);
            cval = fv * cval + iv * gv;
            hval = ov * tanh_(cval);
            hbuf[(par ^ 1) * HID + u] = hval;
            if (writeSeq)
                g_out1[obase + (size_t)tcur * 256] = hval;
        }
        __syncthreads();

        par ^= 1;
        xv0 = nx0; xv1 = nx1; xv2 = nx2; xv3 = nx3;
    }

    if (finalOut != nullptr && kh == 0)
        finalOut[(size_t)b * 256 + (size_t)dir * HID + u] = hval;
}

// ---------------------------------------------------------------------------
// kernel_launch
// ---------------------------------------------------------------------------
extern "C" void kernel_launch(void* const* d_in, const int* in_sizes, int n_in,
                              void* d_out, int out_size)
{
    const float* x       = (const float*)d_in[0];
    const float* Wih_l0f = (const float*)d_in[1];
    const float* Whh_l0f = (const float*)d_in[2];
    const float* bih_l0f = (const float*)d_in[3];
    const float* bhh_l0f = (const float*)d_in[4];
    const float* Wih_l0b = (const float*)d_in[5];
    const float* Whh_l0b = (const float*)d_in[6];
    const float* bih_l0b = (const float*)d_in[7];
    const float* bhh_l0b = (const float*)d_in[8];
    const float* Wih_l1f = (const float*)d_in[9];
    const float* Whh_l1f = (const float*)d_in[10];
    const float* bih_l1f = (const float*)d_in[11];
    const float* bhh_l1f = (const float*)d_in[12];
    const float* Wih_l1b = (const float*)d_in[13];
    const float* Whh_l1b = (const float*)d_in[14];
    const float* bih_l1b = (const float*)d_in[15];
    const float* bhh_l1b = (const float*)d_in[16];

    float* out = (float*)d_out;

    cudaFuncSetAttribute(lstm_scan_kernel,
                         cudaFuncAttributeMaxDynamicSharedMemorySize, SCAN_SMEM);

    dim3 ggrid(1024 / BN, BT / BM);   // (8, 1024)

    // Layer 0 input projection: x[BT,32] -> g_xp[BT,1024]
    proj_gemm_kernel<<<ggrid, 256>>>(x, 32, /*use_out1=*/0,
                                     Wih_l0f, Wih_l0b,
                                     bih_l0f, bhh_l0f, bih_l0b, bhh_l0b);

    // Layer 0 scan: g_xp -> g_out1[BT,256]
    lstm_scan_kernel<<<dim3(BB, 2), 256, SCAN_SMEM>>>(
        Whh_l0f, Whh_l0b, /*writeSeq=*/1, /*finalOut=*/nullptr);

    // Layer 1 input projection: g_out1[BT,256] -> g_xp[BT,1024]
    proj_gemm_kernel<<<ggrid, 256>>>(nullptr, 256, /*use_out1=*/1,
                                     Wih_l1f, Wih_l1b,
                                     bih_l1f, bhh_l1f, bih_l1b, bhh_l1b);

    // Layer 1 scan: g_xp -> final hidden states in d_out[64,256]
    lstm_scan_kernel<<<dim3(BB, 2), 256, SCAN_SMEM>>>(
        Whh_l1f, Whh_l1b, /*writeSeq=*/0, /*finalOut=*/out);
}